// round 3
// baseline (speedup 1.0000x reference)
#include <cuda_runtime.h>
#include <float.h>

// ROI adaptive max pool 7x7 via channels-last restage.
// images: [8,256,56,56] f32; rois: [256,4] f32; roi_idx: [256] i32
// out: [256,256,7,7] f32
//
// K1: per-ROI bin bounds table (kills magic-divides in hot loop).
// K2: transpose images -> g_timg [n][hw][c] (channels-last, 25.7MB scratch).
// K3: pool. lanes = channel-quads (float4): 100% lane efficiency, zero
//     divergence (each warp = one uniform bin-slice), coalesced 512B loads.
//     Output staged in smem, written back as coalesced float4 runs.

#define Nn 8
#define Cc 256
#define Hc 56
#define Wc 56
#define HWc (Hc * Wc)   // 3136
#define Rc 256
#define OUTN 7

__device__ float g_timg[Nn * HWc * Cc];   // [n][hw][c]  ~25.7 MB
__device__ int   g_bins[Rc][28];          // ys[7], ye[7], xs[7], xe[7]

__global__ void bins_kernel(const float* __restrict__ rois) {
    const int r = threadIdx.x;
    const float4 rv = ((const float4*)rois)[r];
    const int x1 = (int)floorf(rv.x * (float)Wc);
    const int y1 = (int)floorf(rv.y * (float)Hc);
    const int x2 = (int)ceilf (rv.z * (float)Wc);
    const int y2 = (int)ceilf (rv.w * (float)Hc);
    const int Hr = y2 - y1, Wr = x2 - x1;
    #pragma unroll
    for (int i = 0; i < OUTN; i++) {
        g_bins[r][i]      = y1 + (i * Hr) / OUTN;
        g_bins[r][7 + i]  = y1 + ((i + 1) * Hr + OUTN - 1) / OUTN;  // ceil
        g_bins[r][14 + i] = x1 + (i * Wr) / OUTN;
        g_bins[r][21 + i] = x1 + ((i + 1) * Wr + OUTN - 1) / OUTN;  // ceil
    }
}

// [n][c][hw] -> [n][hw][c], 32x32 tiles, coalesced both sides.
__global__ __launch_bounds__(256) void transpose_kernel(const float* __restrict__ images) {
    __shared__ float tile[32][33];
    const int hw0 = blockIdx.x * 32;
    const int c0  = blockIdx.y * 32;
    const int n   = blockIdx.z;
    const int tx = threadIdx.x, ty = threadIdx.y;

    const float* __restrict__ src = images + (size_t)n * Cc * HWc;
    #pragma unroll
    for (int k = 0; k < 4; k++) {
        const int c = c0 + ty + k * 8;
        tile[ty + k * 8][tx] = src[(size_t)c * HWc + hw0 + tx];
    }
    __syncthreads();
    float* __restrict__ dst = g_timg + (size_t)n * HWc * Cc;
    #pragma unroll
    for (int k = 0; k < 4; k++) {
        const int hw = hw0 + ty + k * 8;
        dst[(size_t)hw * Cc + c0 + tx] = tile[tx][ty + k * 8];
    }
}

// grid (2, 256): (channel-half, roi). block (32, 8): tx = channel-quad, ty = bin slice.
__global__ __launch_bounds__(256) void pool_kernel(const int* __restrict__ roi_idx,
                                                   float* __restrict__ out) {
    __shared__ int   sb[28];
    __shared__ float sout[128 * 49];

    const int r   = blockIdx.y;
    const int cg  = blockIdx.x;
    const int tx  = threadIdx.x;          // 0..31 quad
    const int ty  = threadIdx.y;          // 0..7  bin slice (warp-uniform)
    const int tid = ty * 32 + tx;

    if (tid < 28) sb[tid] = g_bins[r][tid];
    __syncthreads();

    const int n = roi_idx[r];
    // float4 view: element (n, hw, c) at n*HWc*64 + hw*64 + c/4
    const float4* __restrict__ img4 =
        (const float4*)g_timg + (size_t)n * HWc * (Cc / 4) + cg * 32 + tx;

    for (int b = ty; b < OUTN * OUTN; b += 8) {
        const int i = (b * 37) >> 8;      // b/7 for b<=48
        const int j = b - i * 7;
        const int ys = sb[i],      ye = sb[7 + i];
        const int xs = sb[14 + j], xe = sb[21 + j];
        float4 m = make_float4(-FLT_MAX, -FLT_MAX, -FLT_MAX, -FLT_MAX);
        for (int y = ys; y < ye; y++) {
            const float4* row = img4 + (size_t)(y * Wc + xs) * (Cc / 4);
            #pragma unroll 2
            for (int x = xs; x < xe; x++) {
                const float4 v = *row;
                m.x = fmaxf(m.x, v.x);
                m.y = fmaxf(m.y, v.y);
                m.z = fmaxf(m.z, v.z);
                m.w = fmaxf(m.w, v.w);
                row += Cc / 4;
            }
        }
        const int cl = tx * 4;
        sout[(cl + 0) * 49 + b] = m.x;
        sout[(cl + 1) * 49 + b] = m.y;
        sout[(cl + 2) * 49 + b] = m.z;
        sout[(cl + 3) * 49 + b] = m.w;
    }
    __syncthreads();

    // Coalesced float4 writeback of this block's contiguous [128ch x 49] slab.
    float4* __restrict__ og = (float4*)(out + ((size_t)r * Cc + cg * 128) * 49);
    const float4* __restrict__ so4 = (const float4*)sout;
    for (int idx = tid; idx < 128 * 49 / 4; idx += 256)
        og[idx] = so4[idx];
}

extern "C" void kernel_launch(void* const* d_in, const int* in_sizes, int n_in,
                              void* d_out, int out_size) {
    const float* images  = (const float*)d_in[0];
    const float* rois    = (const float*)d_in[1];
    const int*   roi_idx = (const int*)d_in[2];
    float* out = (float*)d_out;

    bins_kernel<<<1, Rc>>>(rois);
    transpose_kernel<<<dim3(HWc / 32, Cc / 32, Nn), dim3(32, 8)>>>(images);
    pool_kernel<<<dim3(2, Rc), dim3(32, 8)>>>(roi_idx, out);
}

// round 4
// speedup vs baseline: 1.9143x; 1.9143x over previous
#include <cuda_runtime.h>
#include <float.h>

// ROI adaptive max pool 7x7 — single kernel, separable, float4, 2 ch/thread.
// images: [8,256,56,56] f32; rois: [256,4] f32; roi_idx: [256] i32
// out: [256,256,7,7] f32
//
// Block = (roi, 16-channel group), blockDim (16,8) = 128 threads.
// Bin bounds computed once per block into shared (28 threads).
// Phase 1: thread (quad tx, ch ty & ty+8) does float4 row loads for 2
//          channels sharing one loop -> 7 row-bin maxes -> shared rowp.
// Phase 2: strided over 784 outputs, col-bin maxes from shared, coalesced STG.

#define Hc 56
#define Wc 56
#define Cc 256
#define Rc 256
#define OUTN 7
#define CPB 16
#define W4 (Wc / 4)   // 14

__global__ __launch_bounds__(128) void roipool_kernel(
    const float* __restrict__ images,
    const float* __restrict__ rois,
    const int* __restrict__ roi_idx,
    float* __restrict__ out)
{
    __shared__ float rowp[CPB][OUTN][60];
    __shared__ int sb[28];   // ys[7] ye[7] xs[7] xe[7]

    const int r  = blockIdx.y;
    const int cg = blockIdx.x;
    const int tx = threadIdx.x;            // 0..15 quad
    const int ty = threadIdx.y;            // 0..7  (channels ty and ty+8)
    const int tid = ty * 16 + tx;

    // ROI bounds (broadcast loads; cheap, once per thread)
    const float4 rv = ((const float4*)rois)[r];
    const int x1 = (int)floorf(rv.x * (float)Wc);
    const int y1 = (int)floorf(rv.y * (float)Hc);
    const int x2 = (int)ceilf (rv.z * (float)Wc);
    const int y2 = (int)ceilf (rv.w * (float)Hc);

    // Bin bounds table: 28 threads, one entry each
    if (tid < 28) {
        const int g = tid / OUTN;          // 0:ys 1:ye 2:xs 3:xe
        const int i = tid - g * OUTN;
        const int Hr = y2 - y1, Wr = x2 - x1;
        int v;
        if (g == 0)      v = y1 + (i * Hr) / OUTN;
        else if (g == 1) v = y1 + ((i + 1) * Hr + OUTN - 1) / OUTN;
        else if (g == 2) v = x1 + (i * Wr) / OUTN;
        else             v = x1 + ((i + 1) * Wr + OUTN - 1) / OUTN;
        sb[tid] = v;
    }
    __syncthreads();

    const int n = roi_idx[r];
    const float* __restrict__ img0 =
        images + (size_t)(n * Cc + cg * CPB + ty) * (Hc * Wc);

    // ---- Phase 1: row-bin maxes, 2 channels x 4 columns per thread ----
    const int qlo = x1 >> 2;
    const int qhi = (x2 + 3) >> 2;
    if (tx >= qlo && tx < qhi) {
        const float4* __restrict__ base0 = (const float4*)img0 + tx;
        const float4* __restrict__ base1 = base0 + 8 * (Hc * W4);  // +8 channels
        #pragma unroll
        for (int i = 0; i < OUTN; i++) {
            const int s = sb[i], e = sb[7 + i];
            float4 m0 = make_float4(-FLT_MAX, -FLT_MAX, -FLT_MAX, -FLT_MAX);
            float4 m1 = m0;
            const float4* p0 = base0 + s * W4;
            const float4* p1 = base1 + s * W4;
            #pragma unroll 2
            for (int y = s; y < e; y++) {
                const float4 v0 = *p0; p0 += W4;
                const float4 v1 = *p1; p1 += W4;
                m0.x = fmaxf(m0.x, v0.x); m0.y = fmaxf(m0.y, v0.y);
                m0.z = fmaxf(m0.z, v0.z); m0.w = fmaxf(m0.w, v0.w);
                m1.x = fmaxf(m1.x, v1.x); m1.y = fmaxf(m1.y, v1.y);
                m1.z = fmaxf(m1.z, v1.z); m1.w = fmaxf(m1.w, v1.w);
            }
            *(float4*)&rowp[ty][i][tx * 4]     = m0;
            *(float4*)&rowp[ty + 8][i][tx * 4] = m1;
        }
    }
    __syncthreads();

    // ---- Phase 2: col-bin maxes from shared ----
    float* __restrict__ outg = out + ((size_t)r * Cc + cg * CPB) * (OUTN * OUTN);
    #pragma unroll
    for (int o = tid; o < CPB * OUTN * OUTN; o += 128) {
        const int cc = o / (OUTN * OUTN);
        const int ij = o - cc * (OUTN * OUTN);
        const int i = ij / OUTN;
        const int j = ij - i * OUTN;
        const int s = sb[14 + j], e = sb[21 + j];
        float m = -FLT_MAX;
        for (int x = s; x < e; x++)
            m = fmaxf(m, rowp[cc][i][x]);
        outg[o] = m;   // contiguous per stride-pass -> coalesced
    }
}

extern "C" void kernel_launch(void* const* d_in, const int* in_sizes, int n_in,
                              void* d_out, int out_size) {
    const float* images  = (const float*)d_in[0];
    const float* rois    = (const float*)d_in[1];
    const int*   roi_idx = (const int*)d_in[2];
    float* out = (float*)d_out;

    dim3 grid(Cc / CPB, Rc);   // (16, 256) = 4096 blocks
    dim3 block(16, 8);         // 128 threads
    roipool_kernel<<<grid, block>>>(images, rois, roi_idx, out);
}

// round 5
// speedup vs baseline: 1.9910x; 1.0400x over previous
#include <cuda_runtime.h>
#include <float.h>

// ROI adaptive max pool 7x7 — single kernel, separable, float4,
// occupancy-optimized: 1 channel/thread, 256-thread blocks, regs<=32.
// images: [8,256,56,56] f32; rois: [256,4] f32; roi_idx: [256] i32
// out: [256,256,7,7] f32

#define Hc 56
#define Wc 56
#define Cc 256
#define Rc 256
#define OUTN 7
#define CPB 16
#define W4 (Wc / 4)   // 14

__global__ __launch_bounds__(256, 8) void roipool_kernel(
    const float* __restrict__ images,
    const float* __restrict__ rois,
    const int* __restrict__ roi_idx,
    float* __restrict__ out)
{
    __shared__ float rowp[CPB][OUTN][60];
    __shared__ int sb[28];   // ys[7] ye[7] xs[7] xe[7]

    const int r  = blockIdx.y;
    const int cg = blockIdx.x;
    const int tx = threadIdx.x;            // 0..15 quad
    const int ty = threadIdx.y;            // 0..15 channel
    const int tid = ty * 16 + tx;

    const float4 rv = ((const float4*)rois)[r];
    const int x1 = (int)floorf(rv.x * (float)Wc);
    const int y1 = (int)floorf(rv.y * (float)Hc);
    const int x2 = (int)ceilf (rv.z * (float)Wc);
    const int y2 = (int)ceilf (rv.w * (float)Hc);

    // Bin-bounds table: 28 threads, one entry each (kills per-thread divides)
    if (tid < 28) {
        const int g = tid / OUTN;          // 0:ys 1:ye 2:xs 3:xe
        const int i = tid - g * OUTN;
        const int Hr = y2 - y1, Wr = x2 - x1;
        int v;
        if (g == 0)      v = y1 + (i * Hr) / OUTN;
        else if (g == 1) v = y1 + ((i + 1) * Hr + OUTN - 1) / OUTN;
        else if (g == 2) v = x1 + (i * Wr) / OUTN;
        else             v = x1 + ((i + 1) * Wr + OUTN - 1) / OUTN;
        sb[tid] = v;
    }
    __syncthreads();

    const int n = roi_idx[r];
    const float* __restrict__ img =
        images + (size_t)(n * Cc + cg * CPB + ty) * (Hc * Wc);

    // ---- Phase 1: row-bin maxes, 4 columns (one float4) per thread ----
    const int qlo = x1 >> 2;
    const int qhi = (x2 + 3) >> 2;
    if (tx >= qlo && tx < qhi) {
        const float4* __restrict__ base = (const float4*)img + tx;
        #pragma unroll
        for (int i = 0; i < OUTN; i++) {
            const int s = sb[i], e = sb[7 + i];
            float4 m = make_float4(-FLT_MAX, -FLT_MAX, -FLT_MAX, -FLT_MAX);
            const float4* p = base + s * W4;
            #pragma unroll 2
            for (int y = s; y < e; y++) {
                const float4 v = *p; p += W4;
                m.x = fmaxf(m.x, v.x);
                m.y = fmaxf(m.y, v.y);
                m.z = fmaxf(m.z, v.z);
                m.w = fmaxf(m.w, v.w);
            }
            *(float4*)&rowp[ty][i][tx * 4] = m;
        }
    }
    __syncthreads();

    // ---- Phase 2: col-bin maxes from shared ----
    float* __restrict__ outg = out + ((size_t)r * Cc + cg * CPB) * (OUTN * OUTN);
    #pragma unroll
    for (int o = tid; o < CPB * OUTN * OUTN; o += 256) {
        const int cc = o / (OUTN * OUTN);
        const int ij = o - cc * (OUTN * OUTN);
        const int i = ij / OUTN;
        const int j = ij - i * OUTN;
        const int s = sb[14 + j], e = sb[21 + j];
        float m = -FLT_MAX;
        for (int x = s; x < e; x++)
            m = fmaxf(m, rowp[cc][i][x]);
        outg[o] = m;   // contiguous per stride-pass -> coalesced
    }
}

extern "C" void kernel_launch(void* const* d_in, const int* in_sizes, int n_in,
                              void* d_out, int out_size) {
    const float* images  = (const float*)d_in[0];
    const float* rois    = (const float*)d_in[1];
    const int*   roi_idx = (const int*)d_in[2];
    float* out = (float*)d_out;

    dim3 grid(Cc / CPB, Rc);   // (16, 256) = 4096 blocks
    dim3 block(16, 16);        // 256 threads
    roipool_kernel<<<grid, block>>>(images, rois, roi_idx, out);
}